// round 8
// baseline (speedup 1.0000x reference)
#include <cuda_runtime.h>
#include <cuda_bf16.h>
#include <cstdint>

#define B_SZ  512
#define NIN   1024
#define NMID  8192
#define NOUT  1000
#define MPAD  1024
#define FAN   64
#define NCOND 2

#define K1 (3 * NIN)      // 3072  concat K for GEMM1
#define K3 (3 * NMID)     // 24576 concat K for GEMM3
#define KSPLIT3 4

// warp-MMA GEMM tiling
#define TBM 128
#define TBN 128
#define TBK 32
#define ROWB 80           // smem row stride bytes (64B data + 16B pad; 20 words -> conflict-free)
#define GEMM_THREADS 256

// ---------------------------------------------------------------------------
// Scratch (static device globals; referenced ONLY inside device code --
// passing them as kernel args from host binds the host shadow, which on
// GB300/ATS silently reads zeros / writes host RAM: the R5/R6 bug)
// ---------------------------------------------------------------------------
__device__ float4 g_act0v[(size_t)NMID * B_SZ / 4];           // fp32 [o][b]
__device__ float4 g_act1v[(size_t)NMID * B_SZ / 4];           // fp32 [o][b]
__device__ float4 g_wf4[NCOND][(size_t)(FAN / 4) * NMID];     // cond w packed
__device__ uint4  g_if4[(size_t)(FAN / 8) * NMID];            // cond idx packed u16
__device__ __nv_bfloat16 g_wi3[(size_t)NMID * K1];            // [Wh|Wl|Wh]
__device__ __nv_bfloat16 g_x3[(size_t)B_SZ * K1];             // [xh|xh|xl]
__device__ __nv_bfloat16 g_wo3[(size_t)MPAD * K3];            // [Wh|Wl|Wh]
__device__ __nv_bfloat16 g_a13[(size_t)B_SZ * K3];            // [ah|ah|al]

// ---------------------------------------------------------------------------
__device__ __forceinline__ void mma16816(float* d,
                                         uint32_t a0, uint32_t a1, uint32_t a2, uint32_t a3,
                                         uint32_t b0, uint32_t b1) {
    asm volatile(
        "mma.sync.aligned.m16n8k16.row.col.f32.bf16.bf16.f32 "
        "{%0,%1,%2,%3}, {%4,%5,%6,%7}, {%8,%9}, {%0,%1,%2,%3};"
        : "+f"(d[0]), "+f"(d[1]), "+f"(d[2]), "+f"(d[3])
        : "r"(a0), "r"(a1), "r"(a2), "r"(a3), "r"(b0), "r"(b1));
}

// ---------------------------------------------------------------------------
// fp32 -> bf16 hi/lo split + K-concat conversion
// WHICH 0: Win  -> g_wi3, pattern [hi|lo|hi], K=NIN
// WHICH 1: x    -> g_x3,  pattern [hi|hi|lo], K=NIN
// WHICH 2: Wout -> g_wo3, pattern [hi|lo|hi], K=NMID, rows padded NOUT->MPAD
// ---------------------------------------------------------------------------
__device__ __forceinline__ void split_bf16(float v, __nv_bfloat16& h, __nv_bfloat16& l) {
    h = __float2bfloat16(v);
    l = __float2bfloat16(v - __bfloat162float(h));
}
template <int WHICH>
__global__ void cvt3_kernel(const float* __restrict__ src) {
    constexpr int K        = (WHICH == 2) ? NMID : NIN;
    constexpr int rowsTot  = (WHICH == 0) ? NMID : (WHICH == 1) ? B_SZ : MPAD;
    constexpr int rowsVal  = (WHICH == 2) ? NOUT : rowsTot;
    __nv_bfloat16* dst = (WHICH == 0) ? g_wi3 : (WHICH == 1) ? g_x3 : g_wo3;

    long long t = blockIdx.x * (long long)blockDim.x + threadIdx.x;
    if (t * 4 >= (long long)rowsTot * K) return;
    int row = (int)((t * 4) / K);
    int col = (int)((t * 4) % K);
    float4 v = (row < rowsVal)
        ? __ldg((const float4*)(src + (size_t)row * K + col))
        : make_float4(0.f, 0.f, 0.f, 0.f);
    __nv_bfloat16 h0, h1, h2, h3, l0, l1, l2, l3;
    split_bf16(v.x, h0, l0); split_bf16(v.y, h1, l1);
    split_bf16(v.z, h2, l2); split_bf16(v.w, h3, l3);
    ushort4 hv = make_ushort4(__bfloat16_as_ushort(h0), __bfloat16_as_ushort(h1),
                              __bfloat16_as_ushort(h2), __bfloat16_as_ushort(h3));
    ushort4 lv = make_ushort4(__bfloat16_as_ushort(l0), __bfloat16_as_ushort(l1),
                              __bfloat16_as_ushort(l2), __bfloat16_as_ushort(l3));
    __nv_bfloat16* base = dst + (size_t)row * (3 * (size_t)K) + col;
    *(ushort4*)(base)         = hv;
    *(ushort4*)(base + K)     = (WHICH == 1) ? hv : lv;   // A-side: lo, B-side: hi
    *(ushort4*)(base + 2 * K) = (WHICH == 1) ? lv : hv;   // A-side: hi, B-side: lo
}

// ---------------------------------------------------------------------------
// cond prep
// ---------------------------------------------------------------------------
__global__ void prep_w_kernel(const float* __restrict__ Wmid) {
    int t = blockIdx.x * blockDim.x + threadIdx.x;
    if (t >= NCOND * (FAN / 4) * NMID) return;
    int phase = t / ((FAN / 4) * NMID);
    int rem = t - phase * (FAN / 4) * NMID;
    int g = rem / NMID, o = rem - g * NMID;
    const float* src = Wmid + (size_t)(phase * NMID + o) * FAN + g * 4;
    g_wf4[phase][(size_t)g * NMID + o] = make_float4(src[0], src[1], src[2], src[3]);
}
__global__ void prep_i_kernel(const int* __restrict__ idx) {
    int t = blockIdx.x * blockDim.x + threadIdx.x;
    if (t >= (FAN / 8) * NMID) return;
    int g = t / NMID, o = t - g * NMID;
    const int* src = idx + (size_t)o * FAN + g * 8;
    uint4 v;
    v.x = (unsigned)(src[0] & (NMID - 1)) | ((unsigned)(src[1] & (NMID - 1)) << 16);
    v.y = (unsigned)(src[2] & (NMID - 1)) | ((unsigned)(src[3] & (NMID - 1)) << 16);
    v.z = (unsigned)(src[4] & (NMID - 1)) | ((unsigned)(src[5] & (NMID - 1)) << 16);
    v.w = (unsigned)(src[6] & (NMID - 1)) | ((unsigned)(src[7] & (NMID - 1)) << 16);
    g_if4[(size_t)g * NMID + o] = v;
}

// ---------------------------------------------------------------------------
// warp-MMA bf16 GEMM: D[m][n] = sum_k A[m][k] * B[n][k]
// MODE 0: A=g_wi3 B=g_x3  Ks=K1, out: g_act0[m*B_SZ+n] = relu(D + bias[m])
// MODE 1: A=g_wo3 B=g_a13 Ks=K3, out: atomicAdd(out[n*NOUT+m], D) (split-K)
// ---------------------------------------------------------------------------
template <int MODE>
__global__ __launch_bounds__(GEMM_THREADS) void mma_gemm(
    const float* __restrict__ bias, float* __restrict__ outp, int kIters)
{
    const __nv_bfloat16* __restrict__ A = (MODE == 0) ? g_wi3 : g_wo3;
    const __nv_bfloat16* __restrict__ B = (MODE == 0) ? g_x3 : g_a13;
    float* out = (MODE == 0) ? (float*)g_act0v : outp;
    const int Ks = (MODE == 0) ? K1 : K3;

    __shared__ __align__(16) char smA[TBM * ROWB];
    __shared__ __align__(16) char smB[TBN * ROWB];

    int tid = threadIdx.x;
    int wid = tid >> 5, lid = tid & 31;
    int g = lid >> 2, t = lid & 3;
    int wm = (wid >> 1) * 32;               // warp M offset in tile
    int wn = (wid & 1) * 64;                // warp N offset in tile
    int m0 = blockIdx.y * TBM;
    int n0 = blockIdx.x * TBN;
    int kk0 = blockIdx.z * kIters * TBK;

    // staging: 512 16B-chunks per operand; thread handles chunks tid, tid+256
    int r0 = tid >> 2,          s0 = (tid & 3) * 16;           // bytes
    int r1 = (tid + 256) >> 2,  s1 = ((tid + 256) & 3) * 16;

    uint4 rA0, rA1, rB0, rB1;
    float acc[2][8][4] = {};

#define LDG_CHUNKS(it)                                                          \
    do {                                                                        \
        int kk = kk0 + (it) * TBK;                                              \
        rA0 = __ldg((const uint4*)(A + (size_t)(m0 + r0) * Ks + kk + (s0 >> 1))); \
        rA1 = __ldg((const uint4*)(A + (size_t)(m0 + r1) * Ks + kk + (s1 >> 1))); \
        rB0 = __ldg((const uint4*)(B + (size_t)(n0 + r0) * Ks + kk + (s0 >> 1))); \
        rB1 = __ldg((const uint4*)(B + (size_t)(n0 + r1) * Ks + kk + (s1 >> 1))); \
    } while (0)

    LDG_CHUNKS(0);

    for (int it = 0; it < kIters; it++) {
        __syncthreads();                    // previous compute done everywhere
        *(uint4*)(smA + r0 * ROWB + s0) = rA0;
        *(uint4*)(smA + r1 * ROWB + s1) = rA1;
        *(uint4*)(smB + r0 * ROWB + s0) = rB0;
        *(uint4*)(smB + r1 * ROWB + s1) = rB1;
        __syncthreads();
        if (it + 1 < kIters) LDG_CHUNKS(it + 1);   // hidden under compute below

#pragma unroll
        for (int ks = 0; ks < 2; ks++) {
            int koff = (ks * 16 + 2 * t) * 2;      // byte offset in row
            uint32_t a[2][4];
#pragma unroll
            for (int mi = 0; mi < 2; mi++) {
                const char* base = smA + (wm + mi * 16 + g) * ROWB + koff;
                a[mi][0] = *(const uint32_t*)(base);
                a[mi][1] = *(const uint32_t*)(base + 8 * ROWB);
                a[mi][2] = *(const uint32_t*)(base + 16);
                a[mi][3] = *(const uint32_t*)(base + 8 * ROWB + 16);
            }
#pragma unroll
            for (int nj = 0; nj < 4; nj++) {
                const char* bb = smB + (wn + nj * 16 + g) * ROWB + koff;
                uint32_t b0 = *(const uint32_t*)(bb);
                uint32_t b1 = *(const uint32_t*)(bb + 16);
                uint32_t b2 = *(const uint32_t*)(bb + 8 * ROWB);
                uint32_t b3 = *(const uint32_t*)(bb + 8 * ROWB + 16);
#pragma unroll
                for (int mi = 0; mi < 2; mi++) {
                    mma16816(acc[mi][nj * 2],     a[mi][0], a[mi][1], a[mi][2], a[mi][3], b0, b1);
                    mma16816(acc[mi][nj * 2 + 1], a[mi][0], a[mi][1], a[mi][2], a[mi][3], b2, b3);
                }
            }
        }
    }
#undef LDG_CHUNKS

    // epilogue: c0,c1 at (m, n=2t), c2,c3 at (m+8, n=2t)
    int mrow = g;
    int ncol = t * 2;
#pragma unroll
    for (int mi = 0; mi < 2; mi++) {
        int m = m0 + wm + mi * 16 + mrow;
        if (MODE == 0) {
            float bv0 = bias[m], bv8 = bias[m + 8];
#pragma unroll
            for (int n8 = 0; n8 < 8; n8++) {
                int n = n0 + wn + n8 * 8 + ncol;
                float* c = acc[mi][n8];
                float2 lo = make_float2(fmaxf(c[0] + bv0, 0.f), fmaxf(c[1] + bv0, 0.f));
                float2 hi = make_float2(fmaxf(c[2] + bv8, 0.f), fmaxf(c[3] + bv8, 0.f));
                *(float2*)(out + (size_t)m * B_SZ + n) = lo;
                *(float2*)(out + (size_t)(m + 8) * B_SZ + n) = hi;
            }
        } else {
#pragma unroll
            for (int n8 = 0; n8 < 8; n8++) {
                int n = n0 + wn + n8 * 8 + ncol;
                float* c = acc[mi][n8];
                if (m < NOUT) {
                    atomicAdd(out + (size_t)n * NOUT + m, c[0]);
                    atomicAdd(out + (size_t)(n + 1) * NOUT + m, c[1]);
                }
                if (m + 8 < NOUT) {
                    atomicAdd(out + (size_t)n * NOUT + m + 8, c[2]);
                    atomicAdd(out + (size_t)(n + 1) * NOUT + m + 8, c[3]);
                }
            }
        }
    }
}

// ---------------------------------------------------------------------------
// Condensed layer with software-pipelined metadata loads.
// phase 0: fp32 [o][b] -> fp32 [o][b]
// phase 1: fp32 [o][b] -> bf16 concat [b][3*NMID] (hi|hi|lo)
// ---------------------------------------------------------------------------
__global__ __launch_bounds__(1024) void cond_kernel(int phase, const float* __restrict__ bias) {
    extern __shared__ float4 hs[];   // [NMID]
    const float4* hin = (phase == 0) ? g_act0v : g_act1v;
    const float4* wp = g_wf4[phase];
    int bq = blockIdx.x;
    int b0 = bq * 4;
    int tid = threadIdx.x;

    for (int j = tid; j < NMID; j += 1024)
        hs[j] = __ldg(&hin[(size_t)j * (B_SZ / 4) + bq]);
    __syncthreads();

#pragma unroll
    for (int oi = 0; oi < NMID / 1024; oi++) {
        int o = oi * 1024 + tid;
        float bv = __ldg(&bias[o]);
        float ax = 0.f, ay = 0.f, az = 0.f, aw = 0.f;

        // prologue: fetch metadata for g=0
        uint4  iv = __ldg(&g_if4[o]);
        float4 w0 = __ldg(&wp[o]);
        float4 w1 = __ldg(&wp[(size_t)NMID + o]);

#pragma unroll
        for (int g = 0; g < FAN / 8; g++) {
            // prefetch g+1 metadata; its ~L2 latency hides under the 8 gathers
            uint4 ivn; float4 w0n, w1n;
            if (g + 1 < FAN / 8) {
                ivn = __ldg(&g_if4[(size_t)(g + 1) * NMID + o]);
                w0n = __ldg(&wp[(size_t)(2 * g + 2) * NMID + o]);
                w1n = __ldg(&wp[(size_t)(2 * g + 3) * NMID + o]);
            }
            float4 h0 = hs[iv.x & 0xffff];
            float4 h1 = hs[iv.x >> 16];
            float4 h2 = hs[iv.y & 0xffff];
            float4 h3 = hs[iv.y >> 16];
            float4 h4 = hs[iv.z & 0xffff];
            float4 h5 = hs[iv.z >> 16];
            float4 h6 = hs[iv.w & 0xffff];
            float4 h7 = hs[iv.w >> 16];
            ax = fmaf(w0.x, h0.x, ax); ay = fmaf(w0.x, h0.y, ay);
            az = fmaf(w0.x, h0.z, az); aw = fmaf(w0.x, h0.w, aw);
            ax = fmaf(w0.y, h1.x, ax); ay = fmaf(w0.y, h1.y, ay);
            az = fmaf(w0.y, h1.z, az); aw = fmaf(w0.y, h1.w, aw);
            ax = fmaf(w0.z, h2.x, ax); ay = fmaf(w0.z, h2.y, ay);
            az = fmaf(w0.z, h2.z, az); aw = fmaf(w0.z, h2.w, aw);
            ax = fmaf(w0.w, h3.x, ax); ay = fmaf(w0.w, h3.y, ay);
            az = fmaf(w0.w, h3.z, az); aw = fmaf(w0.w, h3.w, aw);
            ax = fmaf(w1.x, h4.x, ax); ay = fmaf(w1.x, h4.y, ay);
            az = fmaf(w1.x, h4.z, az); aw = fmaf(w1.x, h4.w, aw);
            ax = fmaf(w1.y, h5.x, ax); ay = fmaf(w1.y, h5.y, ay);
            az = fmaf(w1.y, h5.z, az); aw = fmaf(w1.y, h5.w, aw);
            ax = fmaf(w1.z, h6.x, ax); ay = fmaf(w1.z, h6.y, ay);
            az = fmaf(w1.z, h6.z, az); aw = fmaf(w1.z, h6.w, aw);
            ax = fmaf(w1.w, h7.x, ax); ay = fmaf(w1.w, h7.y, ay);
            az = fmaf(w1.w, h7.z, az); aw = fmaf(w1.w, h7.w, aw);
            iv = ivn; w0 = w0n; w1 = w1n;
        }
        float4 r;
        r.x = fmaxf(ax + bv, 0.f); r.y = fmaxf(ay + bv, 0.f);
        r.z = fmaxf(az + bv, 0.f); r.w = fmaxf(aw + bv, 0.f);
        if (phase == 0) {
            g_act1v[(size_t)o * (B_SZ / 4) + bq] = r;
        } else {
            float vv[4] = {r.x, r.y, r.z, r.w};
#pragma unroll
            for (int i = 0; i < 4; i++) {
                __nv_bfloat16 h, l;
                split_bf16(vv[i], h, l);
                __nv_bfloat16* base = g_a13 + (size_t)(b0 + i) * K3;
                base[o] = h;
                base[NMID + o] = h;
                base[2 * NMID + o] = l;
            }
        }
    }
}

// ---------------------------------------------------------------------------
__global__ void init_out_kernel(const float* __restrict__ bout, float* __restrict__ out) {
    int t = blockIdx.x * blockDim.x + threadIdx.x;
    if (t < B_SZ * NOUT) out[t] = bout[t % NOUT];
}

// ---------------------------------------------------------------------------
extern "C" void kernel_launch(void* const* d_in, const int* in_sizes, int n_in,
                              void* d_out, int out_size) {
    const float* x    = (const float*)d_in[0];
    const float* Win  = (const float*)d_in[1];
    const float* bin  = (const float*)d_in[2];
    const float* Wmid = (const float*)d_in[3];
    const float* bmid = (const float*)d_in[4];
    const float* Wout = (const float*)d_in[5];
    const float* bout = (const float*)d_in[6];
    const int*   idx  = (const int*)d_in[7];    // int32 (JAX x64 disabled)
    float* out = (float*)d_out;

    cudaFuncSetAttribute(cond_kernel, cudaFuncAttributeMaxDynamicSharedMemorySize, 131072);

    // conversions + cond prep (scratch globals bound inside device code)
    cvt3_kernel<0><<<((size_t)NMID * NIN / 4 + 255) / 256, 256>>>(Win);
    cvt3_kernel<1><<<((size_t)B_SZ * NIN / 4 + 255) / 256, 256>>>(x);
    cvt3_kernel<2><<<((size_t)MPAD * NMID / 4 + 255) / 256, 256>>>(Wout);
    prep_w_kernel<<<(NCOND * (FAN / 4) * NMID + 255) / 256, 256>>>(Wmid);
    prep_i_kernel<<<((FAN / 8) * NMID + 255) / 256, 256>>>(idx);

    // GEMM1: relu(W_in x^T + b_in) -> g_act0 fp32 [o][b]
    mma_gemm<0><<<dim3(B_SZ / TBN, NMID / TBM, 1), GEMM_THREADS>>>(bin, nullptr, K1 / TBK);

    // condensed layers
    cond_kernel<<<B_SZ / 4, 1024, 131072>>>(0, bmid);
    cond_kernel<<<B_SZ / 4, 1024, 131072>>>(1, bmid + NMID);

    // GEMM3: out[b][m] = act1 . W_out^T + b_out  (split-K=4 -> 128 CTAs, one wave)
    init_out_kernel<<<(B_SZ * NOUT + 255) / 256, 256>>>(bout, out);
    mma_gemm<1><<<dim3(B_SZ / TBN, MPAD / TBM, KSPLIT3), GEMM_THREADS>>>(
        nullptr, out, K3 / (TBK * KSPLIT3));
}

// round 9
// speedup vs baseline: 1.0485x; 1.0485x over previous
#include <cuda_runtime.h>
#include <cuda_bf16.h>
#include <cstdint>

#define B_SZ  512
#define NIN   1024
#define NMID  8192
#define NOUT  1000
#define MPAD  1024
#define FAN   64
#define NCOND 2

#define K1 (3 * NIN)      // 3072  concat K for GEMM1
#define K3 (3 * NMID)     // 24576 concat K for GEMM3

// warp-MMA GEMM tiling
#define TBM 128
#define TBN 128
#define TBK 32
#define ROWB 80           // smem row stride bytes (64B data + 16B pad; 20 words -> conflict-free)
#define GEMM_THREADS 256

// ---------------------------------------------------------------------------
// Scratch (static device globals; referenced ONLY inside device code --
// passing them as kernel args from host binds the host shadow, which on
// GB300/ATS silently reads zeros / writes host RAM: the R5/R6 bug)
// ---------------------------------------------------------------------------
__device__ float4 g_act0v[(size_t)NMID * B_SZ / 4];           // fp32 [o][b]
__device__ float4 g_act1v[(size_t)NMID * B_SZ / 4];           // fp32 [o][b]
__device__ float4 g_wf4[NCOND][(size_t)(FAN / 4) * NMID];     // cond w packed
__device__ uint4  g_if4[(size_t)(FAN / 8) * NMID];            // cond idx packed u16
__device__ __nv_bfloat16 g_wi3[(size_t)NMID * K1];            // [Wh|Wl|Wh]
__device__ __nv_bfloat16 g_x3[(size_t)B_SZ * K1];             // [xh|xh|xl]
__device__ __nv_bfloat16 g_wo3[(size_t)MPAD * K3];            // [Wh|Wl|Wh]
__device__ __nv_bfloat16 g_a13[(size_t)B_SZ * K3];            // [ah|ah|al]

// ---------------------------------------------------------------------------
__device__ __forceinline__ void mma16816(float* d,
                                         uint32_t a0, uint32_t a1, uint32_t a2, uint32_t a3,
                                         uint32_t b0, uint32_t b1) {
    asm volatile(
        "mma.sync.aligned.m16n8k16.row.col.f32.bf16.bf16.f32 "
        "{%0,%1,%2,%3}, {%4,%5,%6,%7}, {%8,%9}, {%0,%1,%2,%3};"
        : "+f"(d[0]), "+f"(d[1]), "+f"(d[2]), "+f"(d[3])
        : "r"(a0), "r"(a1), "r"(a2), "r"(a3), "r"(b0), "r"(b1));
}

// ---------------------------------------------------------------------------
// fp32 -> bf16 hi/lo split + K-concat conversion
// WHICH 0: Win  -> g_wi3, pattern [hi|lo|hi], K=NIN
// WHICH 1: x    -> g_x3,  pattern [hi|hi|lo], K=NIN
// WHICH 2: Wout -> g_wo3, pattern [hi|lo|hi], K=NMID, rows padded NOUT->MPAD
// ---------------------------------------------------------------------------
__device__ __forceinline__ void split_bf16(float v, __nv_bfloat16& h, __nv_bfloat16& l) {
    h = __float2bfloat16(v);
    l = __float2bfloat16(v - __bfloat162float(h));
}
template <int WHICH>
__global__ void cvt3_kernel(const float* __restrict__ src) {
    constexpr int K        = (WHICH == 2) ? NMID : NIN;
    constexpr int rowsTot  = (WHICH == 0) ? NMID : (WHICH == 1) ? B_SZ : MPAD;
    constexpr int rowsVal  = (WHICH == 2) ? NOUT : rowsTot;
    __nv_bfloat16* dst = (WHICH == 0) ? g_wi3 : (WHICH == 1) ? g_x3 : g_wo3;

    long long t = blockIdx.x * (long long)blockDim.x + threadIdx.x;
    if (t * 4 >= (long long)rowsTot * K) return;
    int row = (int)((t * 4) / K);
    int col = (int)((t * 4) % K);
    float4 v = (row < rowsVal)
        ? __ldg((const float4*)(src + (size_t)row * K + col))
        : make_float4(0.f, 0.f, 0.f, 0.f);
    __nv_bfloat16 h0, h1, h2, h3, l0, l1, l2, l3;
    split_bf16(v.x, h0, l0); split_bf16(v.y, h1, l1);
    split_bf16(v.z, h2, l2); split_bf16(v.w, h3, l3);
    ushort4 hv = make_ushort4(__bfloat16_as_ushort(h0), __bfloat16_as_ushort(h1),
                              __bfloat16_as_ushort(h2), __bfloat16_as_ushort(h3));
    ushort4 lv = make_ushort4(__bfloat16_as_ushort(l0), __bfloat16_as_ushort(l1),
                              __bfloat16_as_ushort(l2), __bfloat16_as_ushort(l3));
    __nv_bfloat16* base = dst + (size_t)row * (3 * (size_t)K) + col;
    *(ushort4*)(base)         = hv;
    *(ushort4*)(base + K)     = (WHICH == 1) ? hv : lv;   // A-side: lo, B-side: hi
    *(ushort4*)(base + 2 * K) = (WHICH == 1) ? lv : hv;   // A-side: hi, B-side: lo
}

// ---------------------------------------------------------------------------
// cond prep
// ---------------------------------------------------------------------------
__global__ void prep_w_kernel(const float* __restrict__ Wmid) {
    int t = blockIdx.x * blockDim.x + threadIdx.x;
    if (t >= NCOND * (FAN / 4) * NMID) return;
    int phase = t / ((FAN / 4) * NMID);
    int rem = t - phase * (FAN / 4) * NMID;
    int g = rem / NMID, o = rem - g * NMID;
    const float* src = Wmid + (size_t)(phase * NMID + o) * FAN + g * 4;
    g_wf4[phase][(size_t)g * NMID + o] = make_float4(src[0], src[1], src[2], src[3]);
}
__global__ void prep_i_kernel(const int* __restrict__ idx) {
    int t = blockIdx.x * blockDim.x + threadIdx.x;
    if (t >= (FAN / 8) * NMID) return;
    int g = t / NMID, o = t - g * NMID;
    const int* src = idx + (size_t)o * FAN + g * 8;
    uint4 v;
    v.x = (unsigned)(src[0] & (NMID - 1)) | ((unsigned)(src[1] & (NMID - 1)) << 16);
    v.y = (unsigned)(src[2] & (NMID - 1)) | ((unsigned)(src[3] & (NMID - 1)) << 16);
    v.z = (unsigned)(src[4] & (NMID - 1)) | ((unsigned)(src[5] & (NMID - 1)) << 16);
    v.w = (unsigned)(src[6] & (NMID - 1)) | ((unsigned)(src[7] & (NMID - 1)) << 16);
    g_if4[(size_t)g * NMID + o] = v;
}

// ---------------------------------------------------------------------------
// warp-MMA bf16 GEMM: D[m][n] = sum_k A[m][k] * B[n][k]
// Double-buffered smem, ONE __syncthreads per K-iter:
//   iter it: LDG(it+1) -> regs; compute buf[it&1]; STS regs -> buf[(it+1)&1]; sync
// MODE 0: A=g_wi3 B=g_x3  Ks=K1, out: g_act0[m*B_SZ+n] = relu(D + bias[m])
// MODE 1: A=g_wo3 B=g_a13 Ks=K3, out: atomicAdd(out[n*NOUT+m], D) (split-K)
// ---------------------------------------------------------------------------
template <int MODE>
__global__ __launch_bounds__(GEMM_THREADS) void mma_gemm(
    const float* __restrict__ bias, float* __restrict__ outp, int kIters)
{
    const __nv_bfloat16* __restrict__ A = (MODE == 0) ? g_wi3 : g_wo3;
    const __nv_bfloat16* __restrict__ B = (MODE == 0) ? g_x3 : g_a13;
    float* out = (MODE == 0) ? (float*)g_act0v : outp;
    const int Ks = (MODE == 0) ? K1 : K3;

    __shared__ __align__(16) char smA[2][TBM * ROWB];
    __shared__ __align__(16) char smB[2][TBN * ROWB];

    int tid = threadIdx.x;
    int wid = tid >> 5, lid = tid & 31;
    int g = lid >> 2, t = lid & 3;
    int wm = (wid >> 1) * 32;               // warp M offset in tile
    int wn = (wid & 1) * 64;                // warp N offset in tile
    int m0 = blockIdx.y * TBM;
    int n0 = blockIdx.x * TBN;
    int kk0 = blockIdx.z * kIters * TBK;

    // staging: 512 16B-chunks per operand; thread handles chunks tid, tid+256
    int r0 = tid >> 2,          s0 = (tid & 3) * 16;           // bytes
    int r1 = (tid + 256) >> 2,  s1 = ((tid + 256) & 3) * 16;

    uint4 rA0, rA1, rB0, rB1;
    float acc[2][8][4] = {};

#define LDG_CHUNKS(it)                                                          \
    do {                                                                        \
        int kk = kk0 + (it) * TBK;                                              \
        rA0 = __ldg((const uint4*)(A + (size_t)(m0 + r0) * Ks + kk + (s0 >> 1))); \
        rA1 = __ldg((const uint4*)(A + (size_t)(m0 + r1) * Ks + kk + (s1 >> 1))); \
        rB0 = __ldg((const uint4*)(B + (size_t)(n0 + r0) * Ks + kk + (s0 >> 1))); \
        rB1 = __ldg((const uint4*)(B + (size_t)(n0 + r1) * Ks + kk + (s1 >> 1))); \
    } while (0)

#define STS_CHUNKS(p)                                                           \
    do {                                                                        \
        *(uint4*)(smA[p] + r0 * ROWB + s0) = rA0;                               \
        *(uint4*)(smA[p] + r1 * ROWB + s1) = rA1;                               \
        *(uint4*)(smB[p] + r0 * ROWB + s0) = rB0;                               \
        *(uint4*)(smB[p] + r1 * ROWB + s1) = rB1;                               \
    } while (0)

    LDG_CHUNKS(0);
    STS_CHUNKS(0);
    __syncthreads();

    for (int it = 0; it < kIters; it++) {
        int p = it & 1;
        bool more = (it + 1 < kIters);
        if (more) LDG_CHUNKS(it + 1);       // latency hidden under compute below

#pragma unroll
        for (int ks = 0; ks < 2; ks++) {
            int koff = (ks * 16 + 2 * t) * 2;      // byte offset in row
            uint32_t a[2][4];
#pragma unroll
            for (int mi = 0; mi < 2; mi++) {
                const char* base = smA[p] + (wm + mi * 16 + g) * ROWB + koff;
                a[mi][0] = *(const uint32_t*)(base);
                a[mi][1] = *(const uint32_t*)(base + 8 * ROWB);
                a[mi][2] = *(const uint32_t*)(base + 16);
                a[mi][3] = *(const uint32_t*)(base + 8 * ROWB + 16);
            }
#pragma unroll
            for (int nj = 0; nj < 4; nj++) {
                const char* bb = smB[p] + (wn + nj * 16 + g) * ROWB + koff;
                uint32_t b0 = *(const uint32_t*)(bb);
                uint32_t b1 = *(const uint32_t*)(bb + 16);
                uint32_t b2 = *(const uint32_t*)(bb + 8 * ROWB);
                uint32_t b3 = *(const uint32_t*)(bb + 8 * ROWB + 16);
#pragma unroll
                for (int mi = 0; mi < 2; mi++) {
                    mma16816(acc[mi][nj * 2],     a[mi][0], a[mi][1], a[mi][2], a[mi][3], b0, b1);
                    mma16816(acc[mi][nj * 2 + 1], a[mi][0], a[mi][1], a[mi][2], a[mi][3], b2, b3);
                }
            }
        }

        if (more) STS_CHUNKS(p ^ 1);        // other buffer: nobody reads it this iter
        __syncthreads();                    // orders STS visibility + compute completion
    }
#undef LDG_CHUNKS
#undef STS_CHUNKS

    // epilogue: c0,c1 at (m, n=2t), c2,c3 at (m+8, n=2t)
    int mrow = g;
    int ncol = t * 2;
#pragma unroll
    for (int mi = 0; mi < 2; mi++) {
        int m = m0 + wm + mi * 16 + mrow;
        if (MODE == 0) {
            float bv0 = bias[m], bv8 = bias[m + 8];
#pragma unroll
            for (int n8 = 0; n8 < 8; n8++) {
                int n = n0 + wn + n8 * 8 + ncol;
                float* c = acc[mi][n8];
                float2 lo = make_float2(fmaxf(c[0] + bv0, 0.f), fmaxf(c[1] + bv0, 0.f));
                float2 hi = make_float2(fmaxf(c[2] + bv8, 0.f), fmaxf(c[3] + bv8, 0.f));
                *(float2*)(out + (size_t)m * B_SZ + n) = lo;
                *(float2*)(out + (size_t)(m + 8) * B_SZ + n) = hi;
            }
        } else {
#pragma unroll
            for (int n8 = 0; n8 < 8; n8++) {
                int n = n0 + wn + n8 * 8 + ncol;
                float* c = acc[mi][n8];
                if (m < NOUT) {
                    atomicAdd(out + (size_t)n * NOUT + m, c[0]);
                    atomicAdd(out + (size_t)(n + 1) * NOUT + m, c[1]);
                }
                if (m + 8 < NOUT) {
                    atomicAdd(out + (size_t)n * NOUT + m + 8, c[2]);
                    atomicAdd(out + (size_t)(n + 1) * NOUT + m + 8, c[3]);
                }
            }
        }
    }
}

// ---------------------------------------------------------------------------
// Condensed layer (R7-exact: no prefetch -- 1024-thread CTAs cap at 64 regs,
// extra live ranges spill). phase 0: fp32 -> fp32; phase 1: fp32 -> bf16 concat
// ---------------------------------------------------------------------------
__global__ __launch_bounds__(1024) void cond_kernel(int phase, const float* __restrict__ bias) {
    extern __shared__ float4 hs[];   // [NMID]
    const float4* hin = (phase == 0) ? g_act0v : g_act1v;
    const float4* wp = g_wf4[phase];
    int bq = blockIdx.x;
    int b0 = bq * 4;
    int tid = threadIdx.x;

    for (int j = tid; j < NMID; j += 1024)
        hs[j] = hin[(size_t)j * (B_SZ / 4) + bq];
    __syncthreads();

#pragma unroll
    for (int oi = 0; oi < NMID / 1024; oi++) {
        int o = oi * 1024 + tid;
        float ax = 0.f, ay = 0.f, az = 0.f, aw = 0.f;
#pragma unroll
        for (int g = 0; g < FAN / 8; g++) {
            uint4 iv = g_if4[(size_t)g * NMID + o];
            float4 w0 = wp[(size_t)(2 * g) * NMID + o];
            float4 w1 = wp[(size_t)(2 * g + 1) * NMID + o];
            float4 h0 = hs[iv.x & 0xffff];
            float4 h1 = hs[iv.x >> 16];
            float4 h2 = hs[iv.y & 0xffff];
            float4 h3 = hs[iv.y >> 16];
            float4 h4 = hs[iv.z & 0xffff];
            float4 h5 = hs[iv.z >> 16];
            float4 h6 = hs[iv.w & 0xffff];
            float4 h7 = hs[iv.w >> 16];
            ax = fmaf(w0.x, h0.x, ax); ay = fmaf(w0.x, h0.y, ay);
            az = fmaf(w0.x, h0.z, az); aw = fmaf(w0.x, h0.w, aw);
            ax = fmaf(w0.y, h1.x, ax); ay = fmaf(w0.y, h1.y, ay);
            az = fmaf(w0.y, h1.z, az); aw = fmaf(w0.y, h1.w, aw);
            ax = fmaf(w0.z, h2.x, ax); ay = fmaf(w0.z, h2.y, ay);
            az = fmaf(w0.z, h2.z, az); aw = fmaf(w0.z, h2.w, aw);
            ax = fmaf(w0.w, h3.x, ax); ay = fmaf(w0.w, h3.y, ay);
            az = fmaf(w0.w, h3.z, az); aw = fmaf(w0.w, h3.w, aw);
            ax = fmaf(w1.x, h4.x, ax); ay = fmaf(w1.x, h4.y, ay);
            az = fmaf(w1.x, h4.z, az); aw = fmaf(w1.x, h4.w, aw);
            ax = fmaf(w1.y, h5.x, ax); ay = fmaf(w1.y, h5.y, ay);
            az = fmaf(w1.y, h5.z, az); aw = fmaf(w1.y, h5.w, aw);
            ax = fmaf(w1.z, h6.x, ax); ay = fmaf(w1.z, h6.y, ay);
            az = fmaf(w1.z, h6.z, az); aw = fmaf(w1.z, h6.w, aw);
            ax = fmaf(w1.w, h7.x, ax); ay = fmaf(w1.w, h7.y, ay);
            az = fmaf(w1.w, h7.z, az); aw = fmaf(w1.w, h7.w, aw);
        }
        float bv = bias[o];
        float4 r;
        r.x = fmaxf(ax + bv, 0.f); r.y = fmaxf(ay + bv, 0.f);
        r.z = fmaxf(az + bv, 0.f); r.w = fmaxf(aw + bv, 0.f);
        if (phase == 0) {
            g_act1v[(size_t)o * (B_SZ / 4) + bq] = r;
        } else {
            float vv[4] = {r.x, r.y, r.z, r.w};
#pragma unroll
            for (int i = 0; i < 4; i++) {
                __nv_bfloat16 h, l;
                split_bf16(vv[i], h, l);
                __nv_bfloat16* base = g_a13 + (size_t)(b0 + i) * K3;
                base[o] = h;
                base[NMID + o] = h;
                base[2 * NMID + o] = l;
            }
        }
    }
}

// ---------------------------------------------------------------------------
__global__ void init_out_kernel(const float* __restrict__ bout, float* __restrict__ out) {
    int t = blockIdx.x * blockDim.x + threadIdx.x;
    if (t < B_SZ * NOUT) out[t] = bout[t % NOUT];
}

// ---------------------------------------------------------------------------
extern "C" void kernel_launch(void* const* d_in, const int* in_sizes, int n_in,
                              void* d_out, int out_size) {
    const float* x    = (const float*)d_in[0];
    const float* Win  = (const float*)d_in[1];
    const float* bin  = (const float*)d_in[2];
    const float* Wmid = (const float*)d_in[3];
    const float* bmid = (const float*)d_in[4];
    const float* Wout = (const float*)d_in[5];
    const float* bout = (const float*)d_in[6];
    const int*   idx  = (const int*)d_in[7];    // int32 (JAX x64 disabled)
    float* out = (float*)d_out;

    cudaFuncSetAttribute(cond_kernel, cudaFuncAttributeMaxDynamicSharedMemorySize, 131072);

    // conversions + cond prep (scratch globals bound inside device code)
    cvt3_kernel<0><<<((size_t)NMID * NIN / 4 + 255) / 256, 256>>>(Win);
    cvt3_kernel<1><<<((size_t)B_SZ * NIN / 4 + 255) / 256, 256>>>(x);
    cvt3_kernel<2><<<((size_t)MPAD * NMID / 4 + 255) / 256, 256>>>(Wout);
    prep_w_kernel<<<(NCOND * (FAN / 4) * NMID + 255) / 256, 256>>>(Wmid);
    prep_i_kernel<<<((FAN / 8) * NMID + 255) / 256, 256>>>(idx);

    // GEMM1: relu(W_in x^T + b_in) -> g_act0 fp32 [o][b]
    mma_gemm<0><<<dim3(B_SZ / TBN, NMID / TBM, 1), GEMM_THREADS>>>(bin, nullptr, K1 / TBK);

    // condensed layers
    cond_kernel<<<B_SZ / 4, 1024, 131072>>>(0, bmid);
    cond_kernel<<<B_SZ / 4, 1024, 131072>>>(1, bmid + NMID);

    // GEMM3: out[b][m] = act1 . W_out^T + b_out  (split-K=8, atomic)
    init_out_kernel<<<(B_SZ * NOUT + 255) / 256, 256>>>(bout, out);
    mma_gemm<1><<<dim3(B_SZ / TBN, MPAD / TBM, 8), GEMM_THREADS>>>(nullptr, out, K3 / (TBK * 8));
}

// round 10
// speedup vs baseline: 1.3158x; 1.2550x over previous
#include <cuda_runtime.h>
#include <cuda_bf16.h>
#include <cstdint>

#define B_SZ  512
#define NIN   1024
#define NMID  8192
#define NOUT  1000
#define MPAD  1024
#define FAN   64
#define NCOND 2

// warp-MMA GEMM tiling (fp32 staged, hi/lo bf16 split at STS)
#define TBM 128
#define TBN 128
#define TBK 16            // real-K elems per chunk
#define ROWB 48           // bf16 tile row stride bytes (32B data + 16B pad; row*12+t mod 32 covers all banks)
#define GEMM_THREADS 256

// ---------------------------------------------------------------------------
// Scratch (static device globals; referenced ONLY inside device code --
// passing them as kernel args from host binds the host shadow, which on
// GB300/ATS silently reads zeros / writes host RAM: the R5/R6 bug)
// ---------------------------------------------------------------------------
__device__ float4 g_act0v[(size_t)NMID * B_SZ / 4];           // fp32 [o][b]
__device__ float4 g_act1v[(size_t)NMID * B_SZ / 4];           // fp32 [o][b]
__device__ float  g_a1t[(size_t)B_SZ * NMID];                 // fp32 [b][o] (cond1 out, GEMM3 B)
__device__ float4 g_wf4[NCOND][(size_t)(FAN / 4) * NMID];     // cond w packed
__device__ uint4  g_if4[(size_t)(FAN / 8) * NMID];            // cond idx packed u16

// ---------------------------------------------------------------------------
__device__ __forceinline__ void mma16816(float* d,
                                         uint32_t a0, uint32_t a1, uint32_t a2, uint32_t a3,
                                         uint32_t b0, uint32_t b1) {
    asm volatile(
        "mma.sync.aligned.m16n8k16.row.col.f32.bf16.bf16.f32 "
        "{%0,%1,%2,%3}, {%4,%5,%6,%7}, {%8,%9}, {%0,%1,%2,%3};"
        : "+f"(d[0]), "+f"(d[1]), "+f"(d[2]), "+f"(d[3])
        : "r"(a0), "r"(a1), "r"(a2), "r"(a3), "r"(b0), "r"(b1));
}

__device__ __forceinline__ void split_bf16(float v, __nv_bfloat16& h, __nv_bfloat16& l) {
    h = __float2bfloat16(v);
    l = __float2bfloat16(v - __bfloat162float(h));
}
// split float4 into packed hi (ushort4) and lo (ushort4)
__device__ __forceinline__ void split4(float4 v, ushort4& hv, ushort4& lv) {
    __nv_bfloat16 h0, h1, h2, h3, l0, l1, l2, l3;
    split_bf16(v.x, h0, l0); split_bf16(v.y, h1, l1);
    split_bf16(v.z, h2, l2); split_bf16(v.w, h3, l3);
    hv = make_ushort4(__bfloat16_as_ushort(h0), __bfloat16_as_ushort(h1),
                      __bfloat16_as_ushort(h2), __bfloat16_as_ushort(h3));
    lv = make_ushort4(__bfloat16_as_ushort(l0), __bfloat16_as_ushort(l1),
                      __bfloat16_as_ushort(l2), __bfloat16_as_ushort(l3));
}

// ---------------------------------------------------------------------------
// cond prep
// ---------------------------------------------------------------------------
__global__ void prep_w_kernel(const float* __restrict__ Wmid) {
    int t = blockIdx.x * blockDim.x + threadIdx.x;
    if (t >= NCOND * (FAN / 4) * NMID) return;
    int phase = t / ((FAN / 4) * NMID);
    int rem = t - phase * (FAN / 4) * NMID;
    int g = rem / NMID, o = rem - g * NMID;
    const float* src = Wmid + (size_t)(phase * NMID + o) * FAN + g * 4;
    g_wf4[phase][(size_t)g * NMID + o] = make_float4(src[0], src[1], src[2], src[3]);
}
__global__ void prep_i_kernel(const int* __restrict__ idx) {
    int t = blockIdx.x * blockDim.x + threadIdx.x;
    if (t >= (FAN / 8) * NMID) return;
    int g = t / NMID, o = t - g * NMID;
    const int* src = idx + (size_t)o * FAN + g * 8;
    uint4 v;
    v.x = (unsigned)(src[0] & (NMID - 1)) | ((unsigned)(src[1] & (NMID - 1)) << 16);
    v.y = (unsigned)(src[2] & (NMID - 1)) | ((unsigned)(src[3] & (NMID - 1)) << 16);
    v.z = (unsigned)(src[4] & (NMID - 1)) | ((unsigned)(src[5] & (NMID - 1)) << 16);
    v.w = (unsigned)(src[6] & (NMID - 1)) | ((unsigned)(src[7] & (NMID - 1)) << 16);
    g_if4[(size_t)g * NMID + o] = v;
}

// ---------------------------------------------------------------------------
// warp-MMA bf16-split GEMM, fp32 inputs converted during staging:
//   D[m][n] = sum_k A[m][k]*B[n][k], evaluated as Ah*Bh + Ah*Bl + Al*Bh
// MODE 0: A=Win(arg) B=x(arg),    Ks=NIN,  out: g_act0[m*B_SZ+n]=relu(D+bias[m])
// MODE 1: A=Wout(arg) B=g_a1t,    Ks=NMID, out: atomicAdd(out[n*NOUT+m], D); A rows >= NOUT read as 0
// ---------------------------------------------------------------------------
template <int MODE>
__global__ __launch_bounds__(GEMM_THREADS) void mma_gemm(
    const float* __restrict__ Asrc, const float* __restrict__ Bsrc,
    const float* __restrict__ bias, float* __restrict__ outp, int kIters)
{
    const float* __restrict__ A = Asrc;
    const float* __restrict__ B = (MODE == 0) ? Bsrc : (const float*)g_a1t;
    float* out = (MODE == 0) ? (float*)g_act0v : outp;
    const int Ks = (MODE == 0) ? NIN : NMID;

    __shared__ __align__(16) char smAh[TBM * ROWB];
    __shared__ __align__(16) char smAl[TBM * ROWB];
    __shared__ __align__(16) char smBh[TBN * ROWB];
    __shared__ __align__(16) char smBl[TBN * ROWB];

    int tid = threadIdx.x;
    int wid = tid >> 5, lid = tid & 31;
    int g = lid >> 2, t = lid & 3;
    int wm = (wid >> 1) * 32;               // warp M offset in tile
    int wn = (wid & 1) * 64;                // warp N offset in tile
    int m0 = blockIdx.y * TBM;
    int n0 = blockIdx.x * TBN;
    int kk0 = blockIdx.z * kIters * TBK;

    // staging: tile = 128 rows x 16 fp32 (64B) = 512 chunks of 16B; 2 per thread
    int ra0 = tid >> 2,          sa0 = (tid & 3) * 4;            // seg in floats
    int ra1 = (tid + 256) >> 2,  sa1 = ((tid + 256) & 3) * 4;

    float4 fA0, fA1, fB0, fB1;
    float acc[2][8][4] = {};

#define LDG_CHUNKS(it)                                                             \
    do {                                                                           \
        int kk = kk0 + (it) * TBK;                                                 \
        fA0 = (MODE == 1 && m0 + ra0 >= NOUT) ? make_float4(0.f, 0.f, 0.f, 0.f)    \
              : __ldg((const float4*)(A + (size_t)(m0 + ra0) * Ks + kk + sa0));    \
        fA1 = (MODE == 1 && m0 + ra1 >= NOUT) ? make_float4(0.f, 0.f, 0.f, 0.f)    \
              : __ldg((const float4*)(A + (size_t)(m0 + ra1) * Ks + kk + sa1));    \
        fB0 = __ldg((const float4*)(B + (size_t)(n0 + ra0) * Ks + kk + sa0));      \
        fB1 = __ldg((const float4*)(B + (size_t)(n0 + ra1) * Ks + kk + sa1));      \
    } while (0)

#define CVT_STS()                                                                  \
    do {                                                                           \
        ushort4 hv, lv;                                                            \
        split4(fA0, hv, lv);                                                       \
        *(ushort4*)(smAh + ra0 * ROWB + sa0 * 2) = hv;                             \
        *(ushort4*)(smAl + ra0 * ROWB + sa0 * 2) = lv;                             \
        split4(fA1, hv, lv);                                                       \
        *(ushort4*)(smAh + ra1 * ROWB + sa1 * 2) = hv;                             \
        *(ushort4*)(smAl + ra1 * ROWB + sa1 * 2) = lv;                             \
        split4(fB0, hv, lv);                                                       \
        *(ushort4*)(smBh + ra0 * ROWB + sa0 * 2) = hv;                             \
        *(ushort4*)(smBl + ra0 * ROWB + sa0 * 2) = lv;                             \
        split4(fB1, hv, lv);                                                       \
        *(ushort4*)(smBh + ra1 * ROWB + sa1 * 2) = hv;                             \
        *(ushort4*)(smBl + ra1 * ROWB + sa1 * 2) = lv;                             \
    } while (0)

    LDG_CHUNKS(0);

    int koff = 4 * t;                       // byte offset in 32B bf16 row
    for (int it = 0; it < kIters; it++) {
        __syncthreads();                    // previous compute done everywhere
        CVT_STS();
        __syncthreads();
        if (it + 1 < kIters) LDG_CHUNKS(it + 1);   // hidden under compute below

        uint32_t a[2][4];
        // ---- aH fragments (reused for Bh and Bl passes) ----
#pragma unroll
        for (int mi = 0; mi < 2; mi++) {
            const char* base = smAh + (wm + mi * 16 + g) * ROWB + koff;
            a[mi][0] = *(const uint32_t*)(base);
            a[mi][1] = *(const uint32_t*)(base + 8 * ROWB);
            a[mi][2] = *(const uint32_t*)(base + 16);
            a[mi][3] = *(const uint32_t*)(base + 8 * ROWB + 16);
        }
        // pass 0: aH x bH
#pragma unroll
        for (int nj = 0; nj < 4; nj++) {
            const char* bb = smBh + (wn + nj * 16 + g) * ROWB + koff;
            uint32_t b0 = *(const uint32_t*)(bb);
            uint32_t b1 = *(const uint32_t*)(bb + 16);
            uint32_t b2 = *(const uint32_t*)(bb + 8 * ROWB);
            uint32_t b3 = *(const uint32_t*)(bb + 8 * ROWB + 16);
#pragma unroll
            for (int mi = 0; mi < 2; mi++) {
                mma16816(acc[mi][nj * 2],     a[mi][0], a[mi][1], a[mi][2], a[mi][3], b0, b1);
                mma16816(acc[mi][nj * 2 + 1], a[mi][0], a[mi][1], a[mi][2], a[mi][3], b2, b3);
            }
        }
        // pass 1: aH x bL
#pragma unroll
        for (int nj = 0; nj < 4; nj++) {
            const char* bb = smBl + (wn + nj * 16 + g) * ROWB + koff;
            uint32_t b0 = *(const uint32_t*)(bb);
            uint32_t b1 = *(const uint32_t*)(bb + 16);
            uint32_t b2 = *(const uint32_t*)(bb + 8 * ROWB);
            uint32_t b3 = *(const uint32_t*)(bb + 8 * ROWB + 16);
#pragma unroll
            for (int mi = 0; mi < 2; mi++) {
                mma16816(acc[mi][nj * 2],     a[mi][0], a[mi][1], a[mi][2], a[mi][3], b0, b1);
                mma16816(acc[mi][nj * 2 + 1], a[mi][0], a[mi][1], a[mi][2], a[mi][3], b2, b3);
            }
        }
        // ---- aL fragments ----
#pragma unroll
        for (int mi = 0; mi < 2; mi++) {
            const char* base = smAl + (wm + mi * 16 + g) * ROWB + koff;
            a[mi][0] = *(const uint32_t*)(base);
            a[mi][1] = *(const uint32_t*)(base + 8 * ROWB);
            a[mi][2] = *(const uint32_t*)(base + 16);
            a[mi][3] = *(const uint32_t*)(base + 8 * ROWB + 16);
        }
        // pass 2: aL x bH
#pragma unroll
        for (int nj = 0; nj < 4; nj++) {
            const char* bb = smBh + (wn + nj * 16 + g) * ROWB + koff;
            uint32_t b0 = *(const uint32_t*)(bb);
            uint32_t b1 = *(const uint32_t*)(bb + 16);
            uint32_t b2 = *(const uint32_t*)(bb + 8 * ROWB);
            uint32_t b3 = *(const uint32_t*)(bb + 8 * ROWB + 16);
#pragma unroll
            for (int mi = 0; mi < 2; mi++) {
                mma16816(acc[mi][nj * 2],     a[mi][0], a[mi][1], a[mi][2], a[mi][3], b0, b1);
                mma16816(acc[mi][nj * 2 + 1], a[mi][0], a[mi][1], a[mi][2], a[mi][3], b2, b3);
            }
        }
    }
#undef LDG_CHUNKS
#undef CVT_STS

    // epilogue: c0,c1 at (m, n=2t), c2,c3 at (m+8, n=2t)
    int mrow = g;
    int ncol = t * 2;
#pragma unroll
    for (int mi = 0; mi < 2; mi++) {
        int m = m0 + wm + mi * 16 + mrow;
        if (MODE == 0) {
            float bv0 = bias[m], bv8 = bias[m + 8];
#pragma unroll
            for (int n8 = 0; n8 < 8; n8++) {
                int n = n0 + wn + n8 * 8 + ncol;
                float* c = acc[mi][n8];
                float2 lo = make_float2(fmaxf(c[0] + bv0, 0.f), fmaxf(c[1] + bv0, 0.f));
                float2 hi = make_float2(fmaxf(c[2] + bv8, 0.f), fmaxf(c[3] + bv8, 0.f));
                *(float2*)(out + (size_t)m * B_SZ + n) = lo;
                *(float2*)(out + (size_t)(m + 8) * B_SZ + n) = hi;
            }
        } else {
#pragma unroll
            for (int n8 = 0; n8 < 8; n8++) {
                int n = n0 + wn + n8 * 8 + ncol;
                float* c = acc[mi][n8];
                if (m < NOUT) {
                    atomicAdd(out + (size_t)n * NOUT + m, c[0]);
                    atomicAdd(out + (size_t)(n + 1) * NOUT + m, c[1]);
                }
                if (m + 8 < NOUT) {
                    atomicAdd(out + (size_t)n * NOUT + m + 8, c[2]);
                    atomicAdd(out + (size_t)(n + 1) * NOUT + m + 8, c[3]);
                }
            }
        }
    }
}

// ---------------------------------------------------------------------------
// Condensed layer (R7-proven). phase 0: fp32 [o][b] -> fp32 [o][b]
//                              phase 1: fp32 [o][b] -> fp32 [b][o] (g_a1t)
// ---------------------------------------------------------------------------
__global__ __launch_bounds__(1024) void cond_kernel(int phase, const float* __restrict__ bias) {
    extern __shared__ float4 hs[];   // [NMID]
    const float4* hin = (phase == 0) ? g_act0v : g_act1v;
    const float4* wp = g_wf4[phase];
    int bq = blockIdx.x;
    int b0 = bq * 4;
    int tid = threadIdx.x;

    for (int j = tid; j < NMID; j += 1024)
        hs[j] = hin[(size_t)j * (B_SZ / 4) + bq];
    __syncthreads();

#pragma unroll
    for (int oi = 0; oi < NMID / 1024; oi++) {
        int o = oi * 1024 + tid;
        float ax = 0.f, ay = 0.f, az = 0.f, aw = 0.f;
#pragma unroll
        for (int g = 0; g < FAN / 8; g++) {
            uint4 iv = g_if4[(size_t)g * NMID + o];
            float4 w0 = wp[(size_t)(2 * g) * NMID + o];
            float4 w1 = wp[(size_t)(2 * g + 1) * NMID + o];
            float4 h0 = hs[iv.x & 0xffff];
            float4 h1 = hs[iv.x >> 16];
            float4 h2 = hs[iv.y & 0xffff];
            float4 h3 = hs[iv.y >> 16];
            float4 h4 = hs[iv.z & 0xffff];
            float4 h5 = hs[iv.z >> 16];
            float4 h6 = hs[iv.w & 0xffff];
            float4 h7 = hs[iv.w >> 16];
            ax = fmaf(w0.x, h0.x, ax); ay = fmaf(w0.x, h0.y, ay);
            az = fmaf(w0.x, h0.z, az); aw = fmaf(w0.x, h0.w, aw);
            ax = fmaf(w0.y, h1.x, ax); ay = fmaf(w0.y, h1.y, ay);
            az = fmaf(w0.y, h1.z, az); aw = fmaf(w0.y, h1.w, aw);
            ax = fmaf(w0.z, h2.x, ax); ay = fmaf(w0.z, h2.y, ay);
            az = fmaf(w0.z, h2.z, az); aw = fmaf(w0.z, h2.w, aw);
            ax = fmaf(w0.w, h3.x, ax); ay = fmaf(w0.w, h3.y, ay);
            az = fmaf(w0.w, h3.z, az); aw = fmaf(w0.w, h3.w, aw);
            ax = fmaf(w1.x, h4.x, ax); ay = fmaf(w1.x, h4.y, ay);
            az = fmaf(w1.x, h4.z, az); aw = fmaf(w1.x, h4.w, aw);
            ax = fmaf(w1.y, h5.x, ax); ay = fmaf(w1.y, h5.y, ay);
            az = fmaf(w1.y, h5.z, az); aw = fmaf(w1.y, h5.w, aw);
            ax = fmaf(w1.z, h6.x, ax); ay = fmaf(w1.z, h6.y, ay);
            az = fmaf(w1.z, h6.z, az); aw = fmaf(w1.z, h6.w, aw);
            ax = fmaf(w1.w, h7.x, ax); ay = fmaf(w1.w, h7.y, ay);
            az = fmaf(w1.w, h7.z, az); aw = fmaf(w1.w, h7.w, aw);
        }
        float bv = bias[o];
        float4 r;
        r.x = fmaxf(ax + bv, 0.f); r.y = fmaxf(ay + bv, 0.f);
        r.z = fmaxf(az + bv, 0.f); r.w = fmaxf(aw + bv, 0.f);
        if (phase == 0) {
            g_act1v[(size_t)o * (B_SZ / 4) + bq] = r;
        } else {
            g_a1t[(size_t)(b0 + 0) * NMID + o] = r.x;
            g_a1t[(size_t)(b0 + 1) * NMID + o] = r.y;
            g_a1t[(size_t)(b0 + 2) * NMID + o] = r.z;
            g_a1t[(size_t)(b0 + 3) * NMID + o] = r.w;
        }
    }
}

// ---------------------------------------------------------------------------
__global__ void init_out_kernel(const float* __restrict__ bout, float* __restrict__ out) {
    int t = blockIdx.x * blockDim.x + threadIdx.x;
    if (t < B_SZ * NOUT) out[t] = bout[t % NOUT];
}

// ---------------------------------------------------------------------------
extern "C" void kernel_launch(void* const* d_in, const int* in_sizes, int n_in,
                              void* d_out, int out_size) {
    const float* x    = (const float*)d_in[0];
    const float* Win  = (const float*)d_in[1];
    const float* bin  = (const float*)d_in[2];
    const float* Wmid = (const float*)d_in[3];
    const float* bmid = (const float*)d_in[4];
    const float* Wout = (const float*)d_in[5];
    const float* bout = (const float*)d_in[6];
    const int*   idx  = (const int*)d_in[7];    // int32 (JAX x64 disabled)
    float* out = (float*)d_out;

    cudaFuncSetAttribute(cond_kernel, cudaFuncAttributeMaxDynamicSharedMemorySize, 131072);

    // cond prep (scratch globals bound inside device code)
    prep_w_kernel<<<(NCOND * (FAN / 4) * NMID + 255) / 256, 256>>>(Wmid);
    prep_i_kernel<<<((FAN / 8) * NMID + 255) / 256, 256>>>(idx);

    // GEMM1: relu(W_in x^T + b_in) -> g_act0 fp32 [o][b]; fp32 staged, split in-kernel
    mma_gemm<0><<<dim3(B_SZ / TBN, NMID / TBM, 1), GEMM_THREADS>>>(
        Win, x, bin, nullptr, NIN / TBK);

    // condensed layers
    cond_kernel<<<B_SZ / 4, 1024, 131072>>>(0, bmid);
    cond_kernel<<<B_SZ / 4, 1024, 131072>>>(1, bmid + NMID);

    // GEMM3: out[b][m] = act1 . W_out^T + b_out  (split-K=8, atomic)
    init_out_kernel<<<(B_SZ * NOUT + 255) / 256, 256>>>(bout, out);
    mma_gemm<1><<<dim3(B_SZ / TBN, MPAD / TBM, 8), GEMM_THREADS>>>(
        Wout, nullptr, nullptr, out, NMID / (TBK * 8));
}